// round 10
// baseline (speedup 1.0000x reference)
#include <cuda_runtime.h>
#include <cuda_bf16.h>
#include <cuda_fp16.h>
#include <math.h>
#include <stdint.h>

// Problem shape (fixed by the dataset)
#define NHEAD 8        // B*nh = 2*4
#define TT    1024
#define NDIM  8192
#define DD    256

// Static scratch (no allocs allowed)
__device__ __half2       g_QH[(size_t)NHEAD * TT * (NDIM / 2)];   // 128 MB hi part (fp16)
__device__ __half2       g_QL[(size_t)NHEAD * TT * (NDIM / 2)];   // 128 MB lo part (fp16)
__device__ __nv_bfloat16 g_SH[(size_t)NHEAD * TT * TT];           // scores hi (16 MB)
__device__ __nv_bfloat16 g_SL[(size_t)NHEAD * TT * TT];           // scores lo (16 MB)
__device__ __nv_bfloat16 g_VtH[(size_t)2 * DD * TT];              // V^T hi [b][d][s]
__device__ __nv_bfloat16 g_VtL[(size_t)2 * DD * TT];              // V^T lo
__device__ float g_rowfac[NHEAD * TT];

// ---------------------------------------------------------------------------
// PTX helpers (plain sm_80+-class instructions only: cp.async, ldmatrix, mma)
// ---------------------------------------------------------------------------
__device__ __forceinline__ uint32_t smem_u32(const void* p) {
    uint32_t a;
    asm("{ .reg .u64 t; cvta.to.shared.u64 t, %1; cvt.u32.u64 %0, t; }"
        : "=r"(a) : "l"(p));
    return a;
}
__device__ __forceinline__ void cp_async16(uint32_t dst, const void* src) {
    asm volatile("cp.async.cg.shared.global [%0], [%1], 16;" :: "r"(dst), "l"(src) : "memory");
}
#define CP_COMMIT() asm volatile("cp.async.commit_group;" ::: "memory")
#define CP_WAIT(n)  asm volatile("cp.async.wait_group %0;" :: "n"(n) : "memory")

__device__ __forceinline__ void ldsm_x4(uint32_t* r, uint32_t addr) {
    asm volatile("ldmatrix.sync.aligned.m8n8.x4.shared.b16 {%0,%1,%2,%3}, [%4];"
                 : "=r"(r[0]), "=r"(r[1]), "=r"(r[2]), "=r"(r[3]) : "r"(addr));
}
__device__ __forceinline__ void mma_bf16(float* c, const uint32_t* a,
                                         uint32_t b0, uint32_t b1) {
    asm volatile("mma.sync.aligned.m16n8k16.row.col.f32.bf16.bf16.f32 "
                 "{%0,%1,%2,%3}, {%4,%5,%6,%7}, {%8,%9}, {%0,%1,%2,%3};"
                 : "+f"(c[0]), "+f"(c[1]), "+f"(c[2]), "+f"(c[3])
                 : "r"(a[0]), "r"(a[1]), "r"(a[2]), "r"(a[3]), "r"(b0), "r"(b1));
}
__device__ __forceinline__ void mma_fp16(float* c, const uint32_t* a,
                                         uint32_t b0, uint32_t b1) {
    asm volatile("mma.sync.aligned.m16n8k16.row.col.f32.f16.f16.f32 "
                 "{%0,%1,%2,%3}, {%4,%5,%6,%7}, {%8,%9}, {%0,%1,%2,%3};"
                 : "+f"(c[0]), "+f"(c[1]), "+f"(c[2]), "+f"(c[3])
                 : "r"(a[0]), "r"(a[1]), "r"(a[2]), "r"(a[3]), "r"(b0), "r"(b1));
}

// ---- scores kernel geometry: KC=32, 4 stages, 3 tiles (AH, AL, BH) --------
#define S_KC 32
#define S_TILE_BYTES (128 * 64)            // 128 rows x 64B (32 fp16)
#define S_STAGE_BYTES (3 * S_TILE_BYTES)   // 24 KB
#define S_NSTAGE 4
#define S_SMEM (S_NSTAGE * S_STAGE_BYTES)  // 96 KB -> 2 CTAs/SM

// ---- out kernel geometry: KC=64, 3 stages, 4 tiles (bf16 3-term path) -----
#define O_KC 64
#define O_TILE_BYTES (128 * 128)
#define O_STAGE_BYTES (4 * O_TILE_BYTES)
#define O_NSTAGE 3
#define O_SMEM (O_NSTAGE * O_STAGE_BYTES)

// ---------------------------------------------------------------------------
// Kernel 1: RoPE + hi/lo fp16 split. One thread per even/odd pair.
// ---------------------------------------------------------------------------
__global__ __launch_bounds__(256) void rope_split_kernel(const float* __restrict__ Q) {
    size_t p = (size_t)blockIdx.x * blockDim.x + threadIdx.x;   // pair index
    int    n2  = (int)(p & (NDIM / 2 - 1));
    size_t row = p >> 12;
    int    t   = (int)(row & (TT - 1));

    const float TWO_PI_F = 6.283185307179586f;
    float freq = exp2f(-(float)n2 * (1.0f / 256.0f)) * (1.0f / TWO_PI_F);
    float ph   = fmodf((float)t * freq, 1.0f) * TWO_PI_F;
    float s, c;
    sincosf(ph, &s, &c);

    float2 v = *reinterpret_cast<const float2*>(Q + row * NDIM + 2 * (size_t)n2);
    float ox = v.x * c - v.y * s;
    float oy = v.y * c + v.x * s;

    __half hx = __float2half(ox);
    __half hy = __float2half(oy);
    float lx = ox - __half2float(hx);
    float ly = oy - __half2float(hy);
    g_QH[p] = __half2(hx, hy);
    g_QL[p] = __half2(__float2half(lx), __float2half(ly));
}

// ---------------------------------------------------------------------------
// Kernel 2: trace gate factor = 0.5 + 0.5*sigmoid(mean_D(traces))
// ---------------------------------------------------------------------------
__global__ __launch_bounds__(256) void gate_kernel(const float* __restrict__ traces) {
    int row = blockIdx.x;
    float v = traces[(size_t)row * DD + threadIdx.x];
    #pragma unroll
    for (int o = 16; o; o >>= 1) v += __shfl_down_sync(0xffffffffu, v, o);
    __shared__ float ws[8];
    if ((threadIdx.x & 31) == 0) ws[threadIdx.x >> 5] = v;
    __syncthreads();
    if (threadIdx.x == 0) {
        float s = 0.f;
        #pragma unroll
        for (int i = 0; i < 8; i++) s += ws[i];
        float m = s * (1.0f / 256.0f);
        g_rowfac[row] = 0.5f + 0.5f * (1.0f / (1.0f + expf(-m)));
    }
}

// ---------------------------------------------------------------------------
// Kernel 2b: V transpose + hi/lo split:  Vt[b][d][s] = V[b][s][d]  (bf16)
// ---------------------------------------------------------------------------
__global__ __launch_bounds__(256) void vsplit_kernel(const float* __restrict__ V) {
    const int b = blockIdx.z, d0 = blockIdx.x * 32, s0 = blockIdx.y * 32;
    __shared__ float tile[32][33];
    const int tx = threadIdx.x, ty = threadIdx.y;
    #pragma unroll
    for (int i = 0; i < 4; i++) {
        int s = s0 + ty + 8 * i;
        tile[ty + 8 * i][tx] = V[((size_t)b * TT + s) * DD + d0 + tx];
    }
    __syncthreads();
    #pragma unroll
    for (int i = 0; i < 4; i++) {
        int d = d0 + ty + 8 * i;
        float v = tile[tx][ty + 8 * i];
        __nv_bfloat16 h = __float2bfloat16(v);
        size_t idx = ((size_t)b * DD + d) * TT + s0 + tx;
        g_VtH[idx] = h;
        g_VtL[idx] = __float2bfloat16(v - __bfloat162float(h));
    }
}

// ---------------------------------------------------------------------------
// Kernel 3: scores via fp16 mma.sync, 2-term split (AH*BH + AL*BH).
// CTA 128x128, 8 warps (warp tile 32x64), KC=32, 4-stage cp.async pipeline
// (3 loads in flight), ONE __syncthreads per k-iter, 96KB smem -> 2 CTAs/SM.
// Tile rows are 64B; swizzle: off = row*64 + ((c ^ (row&3))<<4), c in 0..3.
// ---------------------------------------------------------------------------
__global__ __launch_bounds__(256, 2) void scores_mma_kernel(const float* __restrict__ scale_p,
                                                            float* __restrict__ S) {
    const int js = blockIdx.x, jt = blockIdx.y, head = blockIdx.z;
    const int t0 = jt * 128, s0 = js * 128;
    float* Sh = S + (size_t)head * TT * TT;
    const int tid = threadIdx.x, wid = tid >> 5, lane = tid & 31;

    if (js > jt) {   // strictly above diagonal: zero fill fp32 output only
        for (int i = tid; i < 128 * 32; i += 256) {
            int r = i >> 5, c4 = (i & 31) << 2;
            *reinterpret_cast<float4*>(&Sh[(size_t)(t0 + r) * TT + s0 + c4]) =
                make_float4(0.f, 0.f, 0.f, 0.f);
        }
        return;
    }

    extern __shared__ char smem[];
    const uint32_t sbase = smem_u32(smem);

    const char* pAH = (const char*)g_QH + ((size_t)head * TT + t0) * NDIM * 2;
    const char* pAL = (const char*)g_QL + ((size_t)head * TT + t0) * NDIM * 2;
    const char* pBH = (const char*)g_QH + ((size_t)head * TT + s0) * NDIM * 2;
    const char* srcs[3] = { pAH, pAL, pBH };

    // 3 tiles * 512 chunks / 256 threads = 6 chunks per thread
    auto load_stage = [&](int stage, int k0) {
        uint32_t sb = sbase + stage * S_STAGE_BYTES;
        size_t kb = (size_t)k0 * 2;
        #pragma unroll
        for (int rep = 0; rep < 6; rep++) {
            int idx = tid + rep * 256;
            int tile = idx >> 9, row = (idx >> 2) & 127, c = idx & 3;
            uint32_t dst = sb + tile * S_TILE_BYTES + row * 64 + ((c ^ (row & 3)) << 4);
            cp_async16(dst, srcs[tile] + (size_t)row * (NDIM * 2) + kb + c * 16);
        }
        CP_COMMIT();
    };

    load_stage(0, 0);
    load_stage(1, S_KC);
    load_stage(2, 2 * S_KC);

    const int wm = wid >> 1, wn = wid & 1;
    const int m0 = wm * 32, n0 = wn * 64;
    const int rig  = (lane & 7) + ((lane >> 3) & 1) * 8;  // row-in-group for ldsm
    const int csel = lane >> 4;                           // 16B chunk select (0/1)
    const int xr   = lane & 3;                            // row&3 for swizzle xor

    // Hoisted ldsm offsets (row part) and per-kk swizzle constants
    uint32_t aoff[2], boff[4];
    #pragma unroll
    for (int mt = 0; mt < 2; mt++) aoff[mt] = (uint32_t)(m0 + mt * 16 + rig) * 64;
    #pragma unroll
    for (int nt = 0; nt < 4; nt++) boff[nt] = (uint32_t)(n0 + nt * 16 + rig) * 64;
    uint32_t swzk[2];
    #pragma unroll
    for (int kk = 0; kk < 2; kk++) swzk[kk] = (uint32_t)(((2 * kk + csel) ^ xr) << 4);

    float acc[2][8][4];
    #pragma unroll
    for (int mt = 0; mt < 2; mt++)
        #pragma unroll
        for (int j = 0; j < 8; j++)
            #pragma unroll
            for (int q = 0; q < 4; q++) acc[mt][j][q] = 0.f;

    const int iters = NDIM / S_KC;  // 256
    for (int k = 0; k < iters; k++) {
        const int buf = k & 3;
        // Wait until load(k) complete (up to 2 younger loads may stay in flight)
        if (k + 3 <= iters) { CP_WAIT(2); }
        else if (k + 2 == iters) { CP_WAIT(1); }
        else { CP_WAIT(0); }
        __syncthreads();   // covers cp.async visibility AND buffer reuse hazard
        if (k + 3 < iters) load_stage((k + 3) & 3, (k + 3) * S_KC);

        const uint32_t sb = sbase + buf * S_STAGE_BYTES;
        const uint32_t aH = sb, aL = sb + S_TILE_BYTES, bH = sb + 2 * S_TILE_BYTES;

        #pragma unroll
        for (int kk = 0; kk < 2; kk++) {
            const uint32_t swz = swzk[kk];

            uint32_t ah[2][4], al[2][4];
            #pragma unroll
            for (int mt = 0; mt < 2; mt++) {
                ldsm_x4(ah[mt], aH + aoff[mt] + swz);
                ldsm_x4(al[mt], aL + aoff[mt] + swz);
            }
            uint32_t bh[4][4];
            #pragma unroll
            for (int nt = 0; nt < 4; nt++)
                ldsm_x4(bh[nt], bH + boff[nt] + swz);

            // Pass 1: hi*hi
            #pragma unroll
            for (int mt = 0; mt < 2; mt++)
                #pragma unroll
                for (int nt = 0; nt < 4; nt++) {
                    mma_fp16(acc[mt][2 * nt],     ah[mt], bh[nt][0], bh[nt][2]);
                    mma_fp16(acc[mt][2 * nt + 1], ah[mt], bh[nt][1], bh[nt][3]);
                }
            // Pass 2: lo*hi
            #pragma unroll
            for (int mt = 0; mt < 2; mt++)
                #pragma unroll
                for (int nt = 0; nt < 4; nt++) {
                    mma_fp16(acc[mt][2 * nt],     al[mt], bh[nt][0], bh[nt][2]);
                    mma_fp16(acc[mt][2 * nt + 1], al[mt], bh[nt][1], bh[nt][3]);
                }
        }
    }

    // Epilogue: tril(-1) * (1 + 0.01*exp(-dt/20)*scale) * rowfac
    const float sc = scale_p[0];
    const int lq = lane >> 2, lr = lane & 3;
    __nv_bfloat16* SHh = g_SH + (size_t)head * TT * TT;
    __nv_bfloat16* SLh = g_SL + (size_t)head * TT * TT;
    #pragma unroll
    for (int mt = 0; mt < 2; mt++) {
        const int tr0 = t0 + m0 + mt * 16 + lq;
        const float rf0 = g_rowfac[head * TT + tr0];
        const float rf1 = g_rowfac[head * TT + tr0 + 8];
        #pragma unroll
        for (int j = 0; j < 8; j++) {
            const int scol = s0 + n0 + j * 8 + 2 * lr;
            float2 o0, o1;
            #pragma unroll
            for (int w = 0; w < 2; w++) {
                int s = scol + w;
                float v0 = 0.f, v1 = 0.f;
                if (s < tr0) {
                    float dt = (float)(tr0 - s);
                    v0 = acc[mt][j][w] * (1.0f + 0.01f * __expf(-dt * 0.05f) * sc) * rf0;
                }
                if (s < tr0 + 8) {
                    float dt = (float)(tr0 + 8 - s);
                    v1 = acc[mt][j][2 + w] * (1.0f + 0.01f * __expf(-dt * 0.05f) * sc) * rf1;
                }
                (&o0.x)[w] = v0;
                (&o1.x)[w] = v1;
            }
            *reinterpret_cast<float2*>(&Sh[(size_t)tr0 * TT + scol]) = o0;
            *reinterpret_cast<float2*>(&Sh[(size_t)(tr0 + 8) * TT + scol]) = o1;

            __nv_bfloat16 h0x = __float2bfloat16(o0.x), h0y = __float2bfloat16(o0.y);
            __nv_bfloat16 h1x = __float2bfloat16(o1.x), h1y = __float2bfloat16(o1.y);
            *reinterpret_cast<__nv_bfloat162*>(&SHh[(size_t)tr0 * TT + scol]) =
                __nv_bfloat162(h0x, h0y);
            *reinterpret_cast<__nv_bfloat162*>(&SHh[(size_t)(tr0 + 8) * TT + scol]) =
                __nv_bfloat162(h1x, h1y);
            *reinterpret_cast<__nv_bfloat162*>(&SLh[(size_t)tr0 * TT + scol]) =
                __nv_bfloat162(__float2bfloat16(o0.x - __bfloat162float(h0x)),
                               __float2bfloat16(o0.y - __bfloat162float(h0y)));
            *reinterpret_cast<__nv_bfloat162*>(&SLh[(size_t)(tr0 + 8) * TT + scol]) =
                __nv_bfloat162(__float2bfloat16(o1.x - __bfloat162float(h1x)),
                               __float2bfloat16(o1.y - __bfloat162float(h1y)));
        }
    }
}

// ---------------------------------------------------------------------------
// Kernel 4: output = scores @ V via bf16 split MMA (unchanged 3-pass path).
// ---------------------------------------------------------------------------
__global__ __launch_bounds__(256, 1) void out_mma_kernel(float* __restrict__ O) {
    const int jd = blockIdx.x, jt = blockIdx.y, head = blockIdx.z;
    const int b  = head >> 2;
    const int t0 = jt * 128, d0 = jd * 128;
    const int tid = threadIdx.x, wid = tid >> 5, lane = tid & 31;

    extern __shared__ char smem[];
    const uint32_t sbase = smem_u32(smem);

    const char* pAH = (const char*)(g_SH  + (size_t)head * TT * TT + (size_t)t0 * TT);
    const char* pAL = (const char*)(g_SL  + (size_t)head * TT * TT + (size_t)t0 * TT);
    const char* pBH = (const char*)(g_VtH + ((size_t)b * DD + d0) * TT);
    const char* pBL = (const char*)(g_VtL + ((size_t)b * DD + d0) * TT);
    const char* srcs[4] = { pAH, pAL, pBH, pBL };

    auto load_stage = [&](int stage, int k0) {
        uint32_t sb = sbase + stage * O_STAGE_BYTES;
        size_t kb = (size_t)k0 * 2;
        #pragma unroll
        for (int rep = 0; rep < 16; rep++) {
            int idx = tid + rep * 256;
            int tile = idx >> 10, row = (idx >> 3) & 127, c = idx & 7;
            uint32_t dst = sb + tile * O_TILE_BYTES + row * 128 + ((c ^ (row & 7)) << 4);
            cp_async16(dst, srcs[tile] + (size_t)row * (TT * 2) + kb + c * 16);
        }
        CP_COMMIT();
    };

    const int iters = 2 * (jt + 1);     // (t0+128)/O_KC
    load_stage(0, 0);
    if (iters > 1) load_stage(1, O_KC);

    const int wm = wid >> 1, wn = wid & 1;
    const int m0 = wm * 32, n0 = wn * 64;
    const int rig  = (lane & 7) + ((lane >> 3) & 1) * 8;
    const int csel = lane >> 4;
    const int xr   = lane & 7;

    float acc[2][8][4];
    #pragma unroll
    for (int mt = 0; mt < 2; mt++)
        #pragma unroll
        for (int j = 0; j < 8; j++)
            #pragma unroll
            for (int q = 0; q < 4; q++) acc[mt][j][q] = 0.f;

    for (int k = 0; k < iters; k++) {
        const int buf = k % O_NSTAGE;
        if (k + 1 < iters) { CP_WAIT(1); } else { CP_WAIT(0); }
        __syncthreads();
        if (k + 2 < iters) load_stage((k + 2) % O_NSTAGE, (k + 2) * O_KC);

        const uint32_t sb = sbase + buf * O_STAGE_BYTES;
        const uint32_t aH = sb, aL = sb + O_TILE_BYTES;
        const uint32_t bH = sb + 2 * O_TILE_BYTES, bL = sb + 3 * O_TILE_BYTES;

        #pragma unroll
        for (int kk = 0; kk < 4; kk++) {
            const int c = 2 * kk + csel;
            const uint32_t swz = (uint32_t)((c ^ xr) << 4);

            uint32_t ah[2][4], al[2][4];
            #pragma unroll
            for (int mt = 0; mt < 2; mt++) {
                uint32_t roff = (uint32_t)(m0 + mt * 16 + rig) * 128 + swz;
                ldsm_x4(ah[mt], aH + roff);
                ldsm_x4(al[mt], aL + roff);
            }
            uint32_t bh[4][4], bl[4][4];
            #pragma unroll
            for (int nt = 0; nt < 4; nt++) {
                uint32_t roff = (uint32_t)(n0 + nt * 16 + rig) * 128 + swz;
                ldsm_x4(bh[nt], bH + roff);
                ldsm_x4(bl[nt], bL + roff);
            }
            #pragma unroll
            for (int mt = 0; mt < 2; mt++)
                #pragma unroll
                for (int nt = 0; nt < 4; nt++) {
                    mma_bf16(acc[mt][2 * nt],     ah[mt], bh[nt][0], bh[nt][2]);
                    mma_bf16(acc[mt][2 * nt + 1], ah[mt], bh[nt][1], bh[nt][3]);
                }
            #pragma unroll
            for (int mt = 0; mt < 2; mt++)
                #pragma unroll
                for (int nt = 0; nt < 4; nt++) {
                    mma_bf16(acc[mt][2 * nt],     ah[mt], bl[nt][0], bl[nt][2]);
                    mma_bf16(acc[mt][2 * nt + 1], ah[mt], bl[nt][1], bl[nt][3]);
                }
            #pragma unroll
            for (int mt = 0; mt < 2; mt++)
                #pragma unroll
                for (int nt = 0; nt < 4; nt++) {
                    mma_bf16(acc[mt][2 * nt],     al[mt], bh[nt][0], bh[nt][2]);
                    mma_bf16(acc[mt][2 * nt + 1], al[mt], bh[nt][1], bh[nt][3]);
                }
        }
    }

    const int lq = lane >> 2, lr = lane & 3;
    #pragma unroll
    for (int mt = 0; mt < 2; mt++) {
        const int tr0 = t0 + m0 + mt * 16 + lq;
        #pragma unroll
        for (int j = 0; j < 8; j++) {
            const int dcol = d0 + n0 + j * 8 + 2 * lr;
            float2 o0, o1;
            o0.x = acc[mt][j][0]; o0.y = acc[mt][j][1];
            o1.x = acc[mt][j][2]; o1.y = acc[mt][j][3];
            *reinterpret_cast<float2*>(&O[((size_t)head * TT + tr0) * DD + dcol]) = o0;
            *reinterpret_cast<float2*>(&O[((size_t)head * TT + tr0 + 8) * DD + dcol]) = o1;
        }
    }
}

// ---------------------------------------------------------------------------
extern "C" void kernel_launch(void* const* d_in, const int* in_sizes, int n_in,
                              void* d_out, int out_size) {
    const float* Q      = (const float*)d_in[0];
    const float* V      = (const float*)d_in[1];
    const float* traces = (const float*)d_in[2];
    const float* scale  = (const float*)d_in[3];

    float* out    = (float*)d_out;
    float* scores = out + (size_t)NHEAD * TT * DD;

    cudaFuncSetAttribute(scores_mma_kernel,
                         cudaFuncAttributeMaxDynamicSharedMemorySize, S_SMEM);
    cudaFuncSetAttribute(out_mma_kernel,
                         cudaFuncAttributeMaxDynamicSharedMemorySize, O_SMEM);

    rope_split_kernel<<<(NHEAD * TT * (NDIM / 2)) / 256, 256>>>(Q);
    gate_kernel<<<NHEAD * TT, 256>>>(traces);
    dim3 gv(DD / 32, TT / 32, 2);
    vsplit_kernel<<<gv, dim3(32, 8)>>>(V);
    dim3 gs(TT / 128, TT / 128, NHEAD);
    scores_mma_kernel<<<gs, 256, S_SMEM>>>(scale, scores);
    dim3 go(DD / 128, TT / 128, NHEAD);
    out_mma_kernel<<<go, 256, O_SMEM>>>(out);
}

// round 11
// speedup vs baseline: 1.0651x; 1.0651x over previous
#include <cuda_runtime.h>
#include <cuda_bf16.h>
#include <cuda_fp16.h>
#include <math.h>
#include <stdint.h>

// Problem shape (fixed by the dataset)
#define NHEAD 8        // B*nh = 2*4
#define TT    1024
#define NDIM  8192
#define DD    256

// Static scratch (no allocs allowed)
__device__ __half2       g_QH[(size_t)NHEAD * TT * (NDIM / 2)];   // 128 MB hi part (fp16)
__device__ __half2       g_QL[(size_t)NHEAD * TT * (NDIM / 2)];   // 128 MB lo part (fp16)
__device__ __nv_bfloat16 g_SH[(size_t)NHEAD * TT * TT];           // scores hi (16 MB)
__device__ __nv_bfloat16 g_SL[(size_t)NHEAD * TT * TT];           // scores lo (16 MB)
__device__ __nv_bfloat16 g_VtH[(size_t)2 * DD * TT];              // V^T hi [b][d][s]
__device__ __nv_bfloat16 g_VtL[(size_t)2 * DD * TT];              // V^T lo
__device__ float g_rowfac[NHEAD * TT];

// ---------------------------------------------------------------------------
// PTX helpers (plain sm_80+-class instructions only: cp.async, ldmatrix, mma)
// ---------------------------------------------------------------------------
__device__ __forceinline__ uint32_t smem_u32(const void* p) {
    uint32_t a;
    asm("{ .reg .u64 t; cvta.to.shared.u64 t, %1; cvt.u32.u64 %0, t; }"
        : "=r"(a) : "l"(p));
    return a;
}
__device__ __forceinline__ void cp_async16(uint32_t dst, const void* src) {
    asm volatile("cp.async.cg.shared.global [%0], [%1], 16;" :: "r"(dst), "l"(src) : "memory");
}
#define CP_COMMIT() asm volatile("cp.async.commit_group;" ::: "memory")
#define CP_WAIT(n)  asm volatile("cp.async.wait_group %0;" :: "n"(n) : "memory")

__device__ __forceinline__ void ldsm_x4(uint32_t* r, uint32_t addr) {
    asm volatile("ldmatrix.sync.aligned.m8n8.x4.shared.b16 {%0,%1,%2,%3}, [%4];"
                 : "=r"(r[0]), "=r"(r[1]), "=r"(r[2]), "=r"(r[3]) : "r"(addr));
}
__device__ __forceinline__ void mma_bf16(float* c, const uint32_t* a,
                                         uint32_t b0, uint32_t b1) {
    asm volatile("mma.sync.aligned.m16n8k16.row.col.f32.bf16.bf16.f32 "
                 "{%0,%1,%2,%3}, {%4,%5,%6,%7}, {%8,%9}, {%0,%1,%2,%3};"
                 : "+f"(c[0]), "+f"(c[1]), "+f"(c[2]), "+f"(c[3])
                 : "r"(a[0]), "r"(a[1]), "r"(a[2]), "r"(a[3]), "r"(b0), "r"(b1));
}
__device__ __forceinline__ void mma_fp16(float* c, const uint32_t* a,
                                         uint32_t b0, uint32_t b1) {
    asm volatile("mma.sync.aligned.m16n8k16.row.col.f32.f16.f16.f32 "
                 "{%0,%1,%2,%3}, {%4,%5,%6,%7}, {%8,%9}, {%0,%1,%2,%3};"
                 : "+f"(c[0]), "+f"(c[1]), "+f"(c[2]), "+f"(c[3])
                 : "r"(a[0]), "r"(a[1]), "r"(a[2]), "r"(a[3]), "r"(b0), "r"(b1));
}

// ---- scores kernel geometry: KC=64, 2 stages, 3 tiles (AH, AL, BH) --------
#define S_KC 64
#define S_TILE_BYTES (128 * 128)           // 128 rows x 128B (64 fp16)
#define S_STAGE_BYTES (3 * S_TILE_BYTES)   // 48 KB
#define S_NSTAGE 2
#define S_SMEM (S_NSTAGE * S_STAGE_BYTES)  // 96 KB -> 2 CTAs/SM

// ---- out kernel geometry: KC=64, 3 stages, 4 tiles (bf16 3-term path) -----
#define O_KC 64
#define O_TILE_BYTES (128 * 128)
#define O_STAGE_BYTES (4 * O_TILE_BYTES)
#define O_NSTAGE 3
#define O_SMEM (O_NSTAGE * O_TILE_BYTES * 4)

// ---------------------------------------------------------------------------
// Kernel 1: RoPE + hi/lo fp16 split. One thread per even/odd pair.
// ---------------------------------------------------------------------------
__global__ __launch_bounds__(256) void rope_split_kernel(const float* __restrict__ Q) {
    size_t p = (size_t)blockIdx.x * blockDim.x + threadIdx.x;   // pair index
    int    n2  = (int)(p & (NDIM / 2 - 1));
    size_t row = p >> 12;
    int    t   = (int)(row & (TT - 1));

    const float TWO_PI_F = 6.283185307179586f;
    float freq = exp2f(-(float)n2 * (1.0f / 256.0f)) * (1.0f / TWO_PI_F);
    float ph   = fmodf((float)t * freq, 1.0f) * TWO_PI_F;
    float s, c;
    sincosf(ph, &s, &c);

    float2 v = *reinterpret_cast<const float2*>(Q + row * NDIM + 2 * (size_t)n2);
    float ox = v.x * c - v.y * s;
    float oy = v.y * c + v.x * s;

    __half hx = __float2half(ox);
    __half hy = __float2half(oy);
    float lx = ox - __half2float(hx);
    float ly = oy - __half2float(hy);
    g_QH[p] = __half2(hx, hy);
    g_QL[p] = __half2(__float2half(lx), __float2half(ly));
}

// ---------------------------------------------------------------------------
// Kernel 2: trace gate factor = 0.5 + 0.5*sigmoid(mean_D(traces))
// ---------------------------------------------------------------------------
__global__ __launch_bounds__(256) void gate_kernel(const float* __restrict__ traces) {
    int row = blockIdx.x;
    float v = traces[(size_t)row * DD + threadIdx.x];
    #pragma unroll
    for (int o = 16; o; o >>= 1) v += __shfl_down_sync(0xffffffffu, v, o);
    __shared__ float ws[8];
    if ((threadIdx.x & 31) == 0) ws[threadIdx.x >> 5] = v;
    __syncthreads();
    if (threadIdx.x == 0) {
        float s = 0.f;
        #pragma unroll
        for (int i = 0; i < 8; i++) s += ws[i];
        float m = s * (1.0f / 256.0f);
        g_rowfac[row] = 0.5f + 0.5f * (1.0f / (1.0f + expf(-m)));
    }
}

// ---------------------------------------------------------------------------
// Kernel 2b: V transpose + hi/lo split:  Vt[b][d][s] = V[b][s][d]  (bf16)
// ---------------------------------------------------------------------------
__global__ __launch_bounds__(256) void vsplit_kernel(const float* __restrict__ V) {
    const int b = blockIdx.z, d0 = blockIdx.x * 32, s0 = blockIdx.y * 32;
    __shared__ float tile[32][33];
    const int tx = threadIdx.x, ty = threadIdx.y;
    #pragma unroll
    for (int i = 0; i < 4; i++) {
        int s = s0 + ty + 8 * i;
        tile[ty + 8 * i][tx] = V[((size_t)b * TT + s) * DD + d0 + tx];
    }
    __syncthreads();
    #pragma unroll
    for (int i = 0; i < 4; i++) {
        int d = d0 + ty + 8 * i;
        float v = tile[tx][ty + 8 * i];
        __nv_bfloat16 h = __float2bfloat16(v);
        size_t idx = ((size_t)b * DD + d) * TT + s0 + tx;
        g_VtH[idx] = h;
        g_VtL[idx] = __float2bfloat16(v - __bfloat162float(h));
    }
}

// ---------------------------------------------------------------------------
// Kernel 3: scores via fp16 mma.sync, 2-term split (AH*BH + AL*BH).
// CTA 128x128, 8 warps (warp tile 32x64), KC=64, 2-stage pipeline,
// ONE __syncthreads per iter (wait -> sync -> load(k+1) -> compute),
// 96KB smem + <=128 regs -> 2 CTAs/SM. Diagonal tiles: warps entirely
// above the diagonal skip frag loads + MMAs.
// ---------------------------------------------------------------------------
__global__ __launch_bounds__(256, 2) void scores_mma_kernel(const float* __restrict__ scale_p,
                                                            float* __restrict__ S) {
    const int js = blockIdx.x, jt = blockIdx.y, head = blockIdx.z;
    const int t0 = jt * 128, s0 = js * 128;
    float* Sh = S + (size_t)head * TT * TT;
    const int tid = threadIdx.x, wid = tid >> 5, lane = tid & 31;

    if (js > jt) {   // strictly above diagonal: zero fill fp32 output only
        for (int i = tid; i < 128 * 32; i += 256) {
            int r = i >> 5, c4 = (i & 31) << 2;
            *reinterpret_cast<float4*>(&Sh[(size_t)(t0 + r) * TT + s0 + c4]) =
                make_float4(0.f, 0.f, 0.f, 0.f);
        }
        return;
    }

    extern __shared__ char smem[];
    const uint32_t sbase = smem_u32(smem);

    const char* pAH = (const char*)g_QH + ((size_t)head * TT + t0) * NDIM * 2;
    const char* pAL = (const char*)g_QL + ((size_t)head * TT + t0) * NDIM * 2;
    const char* pBH = (const char*)g_QH + ((size_t)head * TT + s0) * NDIM * 2;
    const char* srcs[3] = { pAH, pAL, pBH };

    // 3 tiles * 1024 chunks / 256 threads = 12 chunks per thread
    auto load_stage = [&](int stage, int k0) {
        uint32_t sb = sbase + stage * S_STAGE_BYTES;
        size_t kb = (size_t)k0 * 2;
        #pragma unroll
        for (int rep = 0; rep < 12; rep++) {
            int idx = tid + rep * 256;
            int tile = idx >> 10, row = (idx >> 3) & 127, c = idx & 7;
            uint32_t dst = sb + tile * S_TILE_BYTES + row * 128 + ((c ^ (row & 7)) << 4);
            cp_async16(dst, srcs[tile] + (size_t)row * (NDIM * 2) + kb + c * 16);
        }
        CP_COMMIT();
    };

    load_stage(0, 0);

    const int wm = wid >> 1, wn = wid & 1;
    const int m0 = wm * 32, n0 = wn * 64;
    const int rig  = (lane & 7) + ((lane >> 3) & 1) * 8;
    const int csel = lane >> 4;
    const int xr   = lane & 7;

    // Diagonal tile: warp tile entirely above diagonal iff n0 >= m0 + 32
    const bool active = !(js == jt && n0 >= m0 + 32);

    // Hoisted ldsm row offsets and per-kk swizzle constants
    uint32_t aoff[2], boff[4];
    #pragma unroll
    for (int mt = 0; mt < 2; mt++) aoff[mt] = (uint32_t)(m0 + mt * 16 + rig) * 128;
    #pragma unroll
    for (int nt = 0; nt < 4; nt++) boff[nt] = (uint32_t)(n0 + nt * 16 + rig) * 128;
    uint32_t swzk[4];
    #pragma unroll
    for (int kk = 0; kk < 4; kk++) swzk[kk] = (uint32_t)(((2 * kk + csel) ^ xr) << 4);

    float acc[2][8][4];
    #pragma unroll
    for (int mt = 0; mt < 2; mt++)
        #pragma unroll
        for (int j = 0; j < 8; j++)
            #pragma unroll
            for (int q = 0; q < 4; q++) acc[mt][j][q] = 0.f;

    const int iters = NDIM / S_KC;  // 128
    for (int k = 0; k < iters; k++) {
        const int buf = k & 1;
        CP_WAIT(0);          // only load(k) is in flight here
        __syncthreads();     // all warps done with buf^1 from iter k-1; load(k) visible
        if (k + 1 < iters) load_stage(buf ^ 1, (k + 1) * S_KC);

        if (active) {
            const uint32_t sb = sbase + buf * S_STAGE_BYTES;
            const uint32_t aH = sb, aL = sb + S_TILE_BYTES, bH = sb + 2 * S_TILE_BYTES;

            #pragma unroll
            for (int kk = 0; kk < 4; kk++) {
                const uint32_t swz = swzk[kk];

                uint32_t ah[2][4], al[2][4];
                #pragma unroll
                for (int mt = 0; mt < 2; mt++) {
                    ldsm_x4(ah[mt], aH + aoff[mt] + swz);
                    ldsm_x4(al[mt], aL + aoff[mt] + swz);
                }
                uint32_t bh[4][4];
                #pragma unroll
                for (int nt = 0; nt < 4; nt++)
                    ldsm_x4(bh[nt], bH + boff[nt] + swz);

                // Pass 1: hi*hi
                #pragma unroll
                for (int mt = 0; mt < 2; mt++)
                    #pragma unroll
                    for (int nt = 0; nt < 4; nt++) {
                        mma_fp16(acc[mt][2 * nt],     ah[mt], bh[nt][0], bh[nt][2]);
                        mma_fp16(acc[mt][2 * nt + 1], ah[mt], bh[nt][1], bh[nt][3]);
                    }
                // Pass 2: lo*hi
                #pragma unroll
                for (int mt = 0; mt < 2; mt++)
                    #pragma unroll
                    for (int nt = 0; nt < 4; nt++) {
                        mma_fp16(acc[mt][2 * nt],     al[mt], bh[nt][0], bh[nt][2]);
                        mma_fp16(acc[mt][2 * nt + 1], al[mt], bh[nt][1], bh[nt][3]);
                    }
            }
        }
    }

    // Epilogue: tril(-1) * (1 + 0.01*exp(-dt/20)*scale) * rowfac
    const float sc = scale_p[0];
    const int lq = lane >> 2, lr = lane & 3;
    __nv_bfloat16* SHh = g_SH + (size_t)head * TT * TT;
    __nv_bfloat16* SLh = g_SL + (size_t)head * TT * TT;
    #pragma unroll
    for (int mt = 0; mt < 2; mt++) {
        const int tr0 = t0 + m0 + mt * 16 + lq;
        const float rf0 = g_rowfac[head * TT + tr0];
        const float rf1 = g_rowfac[head * TT + tr0 + 8];
        #pragma unroll
        for (int j = 0; j < 8; j++) {
            const int scol = s0 + n0 + j * 8 + 2 * lr;
            float2 o0, o1;
            #pragma unroll
            for (int w = 0; w < 2; w++) {
                int s = scol + w;
                float v0 = 0.f, v1 = 0.f;
                if (s < tr0) {
                    float dt = (float)(tr0 - s);
                    v0 = acc[mt][j][w] * (1.0f + 0.01f * __expf(-dt * 0.05f) * sc) * rf0;
                }
                if (s < tr0 + 8) {
                    float dt = (float)(tr0 + 8 - s);
                    v1 = acc[mt][j][2 + w] * (1.0f + 0.01f * __expf(-dt * 0.05f) * sc) * rf1;
                }
                (&o0.x)[w] = v0;
                (&o1.x)[w] = v1;
            }
            *reinterpret_cast<float2*>(&Sh[(size_t)tr0 * TT + scol]) = o0;
            *reinterpret_cast<float2*>(&Sh[(size_t)(tr0 + 8) * TT + scol]) = o1;

            __nv_bfloat16 h0x = __float2bfloat16(o0.x), h0y = __float2bfloat16(o0.y);
            __nv_bfloat16 h1x = __float2bfloat16(o1.x), h1y = __float2bfloat16(o1.y);
            *reinterpret_cast<__nv_bfloat162*>(&SHh[(size_t)tr0 * TT + scol]) =
                __nv_bfloat162(h0x, h0y);
            *reinterpret_cast<__nv_bfloat162*>(&SHh[(size_t)(tr0 + 8) * TT + scol]) =
                __nv_bfloat162(h1x, h1y);
            *reinterpret_cast<__nv_bfloat162*>(&SLh[(size_t)tr0 * TT + scol]) =
                __nv_bfloat162(__float2bfloat16(o0.x - __bfloat162float(h0x)),
                               __float2bfloat16(o0.y - __bfloat162float(h0y)));
            *reinterpret_cast<__nv_bfloat162*>(&SLh[(size_t)(tr0 + 8) * TT + scol]) =
                __nv_bfloat162(__float2bfloat16(o1.x - __bfloat162float(h1x)),
                               __float2bfloat16(o1.y - __bfloat162float(h1y)));
        }
    }
}

// ---------------------------------------------------------------------------
// Kernel 4: output = scores @ V via bf16 split MMA (unchanged 3-pass path).
// ---------------------------------------------------------------------------
__global__ __launch_bounds__(256, 1) void out_mma_kernel(float* __restrict__ O) {
    const int jd = blockIdx.x, jt = blockIdx.y, head = blockIdx.z;
    const int b  = head >> 2;
    const int t0 = jt * 128, d0 = jd * 128;
    const int tid = threadIdx.x, wid = tid >> 5, lane = tid & 31;

    extern __shared__ char smem[];
    const uint32_t sbase = smem_u32(smem);

    const char* pAH = (const char*)(g_SH  + (size_t)head * TT * TT + (size_t)t0 * TT);
    const char* pAL = (const char*)(g_SL  + (size_t)head * TT * TT + (size_t)t0 * TT);
    const char* pBH = (const char*)(g_VtH + ((size_t)b * DD + d0) * TT);
    const char* pBL = (const char*)(g_VtL + ((size_t)b * DD + d0) * TT);
    const char* srcs[4] = { pAH, pAL, pBH, pBL };

    auto load_stage = [&](int stage, int k0) {
        uint32_t sb = sbase + stage * O_STAGE_BYTES;
        size_t kb = (size_t)k0 * 2;
        #pragma unroll
        for (int rep = 0; rep < 16; rep++) {
            int idx = tid + rep * 256;
            int tile = idx >> 10, row = (idx >> 3) & 127, c = idx & 7;
            uint32_t dst = sb + tile * O_TILE_BYTES + row * 128 + ((c ^ (row & 7)) << 4);
            cp_async16(dst, srcs[tile] + (size_t)row * (TT * 2) + kb + c * 16);
        }
        CP_COMMIT();
    };

    const int iters = 2 * (jt + 1);     // (t0+128)/O_KC
    load_stage(0, 0);
    if (iters > 1) load_stage(1, O_KC);

    const int wm = wid >> 1, wn = wid & 1;
    const int m0 = wm * 32, n0 = wn * 64;
    const int rig  = (lane & 7) + ((lane >> 3) & 1) * 8;
    const int csel = lane >> 4;
    const int xr   = lane & 7;

    float acc[2][8][4];
    #pragma unroll
    for (int mt = 0; mt < 2; mt++)
        #pragma unroll
        for (int j = 0; j < 8; j++)
            #pragma unroll
            for (int q = 0; q < 4; q++) acc[mt][j][q] = 0.f;

    for (int k = 0; k < iters; k++) {
        const int buf = k % O_NSTAGE;
        if (k + 1 < iters) { CP_WAIT(1); } else { CP_WAIT(0); }
        __syncthreads();
        if (k + 2 < iters) load_stage((k + 2) % O_NSTAGE, (k + 2) * O_KC);

        const uint32_t sb = sbase + buf * O_STAGE_BYTES;
        const uint32_t aH = sb, aL = sb + O_TILE_BYTES;
        const uint32_t bH = sb + 2 * O_TILE_BYTES, bL = sb + 3 * O_TILE_BYTES;

        #pragma unroll
        for (int kk = 0; kk < 4; kk++) {
            const int c = 2 * kk + csel;
            const uint32_t swz = (uint32_t)((c ^ xr) << 4);

            uint32_t ah[2][4], al[2][4];
            #pragma unroll
            for (int mt = 0; mt < 2; mt++) {
                uint32_t roff = (uint32_t)(m0 + mt * 16 + rig) * 128 + swz;
                ldsm_x4(ah[mt], aH + roff);
                ldsm_x4(al[mt], aL + roff);
            }
            uint32_t bh[4][4], bl[4][4];
            #pragma unroll
            for (int nt = 0; nt < 4; nt++) {
                uint32_t roff = (uint32_t)(n0 + nt * 16 + rig) * 128 + swz;
                ldsm_x4(bh[nt], bH + roff);
                ldsm_x4(bl[nt], bL + roff);
            }
            #pragma unroll
            for (int mt = 0; mt < 2; mt++)
                #pragma unroll
                for (int nt = 0; nt < 4; nt++) {
                    mma_bf16(acc[mt][2 * nt],     ah[mt], bh[nt][0], bh[nt][2]);
                    mma_bf16(acc[mt][2 * nt + 1], ah[mt], bh[nt][1], bh[nt][3]);
                }
            #pragma unroll
            for (int mt = 0; mt < 2; mt++)
                #pragma unroll
                for (int nt = 0; nt < 4; nt++) {
                    mma_bf16(acc[mt][2 * nt],     ah[mt], bl[nt][0], bl[nt][2]);
                    mma_bf16(acc[mt][2 * nt + 1], ah[mt], bl[nt][1], bl[nt][3]);
                }
            #pragma unroll
            for (int mt = 0; mt < 2; mt++)
                #pragma unroll
                for (int nt = 0; nt < 4; nt++) {
                    mma_bf16(acc[mt][2 * nt],     al[mt], bh[nt][0], bh[nt][2]);
                    mma_bf16(acc[mt][2 * nt + 1], al[mt], bh[nt][1], bh[nt][3]);
                }
        }
    }

    const int lq = lane >> 2, lr = lane & 3;
    #pragma unroll
    for (int mt = 0; mt < 2; mt++) {
        const int tr0 = t0 + m0 + mt * 16 + lq;
        #pragma unroll
        for (int j = 0; j < 8; j++) {
            const int dcol = d0 + n0 + j * 8 + 2 * lr;
            float2 o0, o1;
            o0.x = acc[mt][j][0]; o0.y = acc[mt][j][1];
            o1.x = acc[mt][j][2]; o1.y = acc[mt][j][3];
            *reinterpret_cast<float2*>(&O[((size_t)head * TT + tr0) * DD + dcol]) = o0;
            *reinterpret_cast<float2*>(&O[((size_t)head * TT + tr0 + 8) * DD + dcol]) = o1;
        }
    }
}

// ---------------------------------------------------------------------------
extern "C" void kernel_launch(void* const* d_in, const int* in_sizes, int n_in,
                              void* d_out, int out_size) {
    const float* Q      = (const float*)d_in[0];
    const float* V      = (const float*)d_in[1];
    const float* traces = (const float*)d_in[2];
    const float* scale  = (const float*)d_in[3];

    float* out    = (float*)d_out;
    float* scores = out + (size_t)NHEAD * TT * DD;

    cudaFuncSetAttribute(scores_mma_kernel,
                         cudaFuncAttributeMaxDynamicSharedMemorySize, S_SMEM);
    cudaFuncSetAttribute(out_mma_kernel,
                         cudaFuncAttributeMaxDynamicSharedMemorySize, O_SMEM);

    rope_split_kernel<<<(NHEAD * TT * (NDIM / 2)) / 256, 256>>>(Q);
    gate_kernel<<<NHEAD * TT, 256>>>(traces);
    dim3 gv(DD / 32, TT / 32, 2);
    vsplit_kernel<<<gv, dim3(32, 8)>>>(V);
    dim3 gs(TT / 128, TT / 128, NHEAD);
    scores_mma_kernel<<<gs, 256, S_SMEM>>>(scale, scores);
    dim3 go(DD / 128, TT / 128, NHEAD);
    out_mma_kernel<<<go, 256, O_SMEM>>>(out);
}

// round 12
// speedup vs baseline: 1.0954x; 1.0285x over previous
#include <cuda_runtime.h>
#include <cuda_bf16.h>
#include <cuda_fp16.h>
#include <math.h>
#include <stdint.h>

// Problem shape (fixed by the dataset)
#define NHEAD 8        // B*nh = 2*4
#define TT    1024
#define NDIM  8192
#define DD    256

// Static scratch (no allocs allowed)
__device__ __half2       g_QH[(size_t)NHEAD * TT * (NDIM / 2)];   // 128 MB hi part (fp16)
__device__ __half2       g_QL[(size_t)NHEAD * TT * (NDIM / 2)];   // 128 MB lo part (fp16)
__device__ __nv_bfloat16 g_SH[(size_t)NHEAD * TT * TT];           // scores hi (16 MB)
__device__ __nv_bfloat16 g_SL[(size_t)NHEAD * TT * TT];           // scores lo (16 MB)
__device__ __nv_bfloat16 g_VtH[(size_t)2 * DD * TT];              // V^T hi [b][d][s]
__device__ __nv_bfloat16 g_VtL[(size_t)2 * DD * TT];              // V^T lo
__device__ float g_rowfac[NHEAD * TT];

// ---------------------------------------------------------------------------
// PTX helpers (plain sm_80+-class instructions only: cp.async, ldmatrix, mma)
// ---------------------------------------------------------------------------
__device__ __forceinline__ uint32_t smem_u32(const void* p) {
    uint32_t a;
    asm("{ .reg .u64 t; cvta.to.shared.u64 t, %1; cvt.u32.u64 %0, t; }"
        : "=r"(a) : "l"(p));
    return a;
}
__device__ __forceinline__ void cp_async16(uint32_t dst, const void* src) {
    asm volatile("cp.async.cg.shared.global [%0], [%1], 16;" :: "r"(dst), "l"(src) : "memory");
}
#define CP_COMMIT() asm volatile("cp.async.commit_group;" ::: "memory")
#define CP_WAIT(n)  asm volatile("cp.async.wait_group %0;" :: "n"(n) : "memory")

__device__ __forceinline__ void ldsm_x4(uint32_t* r, uint32_t addr) {
    asm volatile("ldmatrix.sync.aligned.m8n8.x4.shared.b16 {%0,%1,%2,%3}, [%4];"
                 : "=r"(r[0]), "=r"(r[1]), "=r"(r[2]), "=r"(r[3]) : "r"(addr));
}
__device__ __forceinline__ void mma_bf16(float* c, const uint32_t* a,
                                         uint32_t b0, uint32_t b1) {
    asm volatile("mma.sync.aligned.m16n8k16.row.col.f32.bf16.bf16.f32 "
                 "{%0,%1,%2,%3}, {%4,%5,%6,%7}, {%8,%9}, {%0,%1,%2,%3};"
                 : "+f"(c[0]), "+f"(c[1]), "+f"(c[2]), "+f"(c[3])
                 : "r"(a[0]), "r"(a[1]), "r"(a[2]), "r"(a[3]), "r"(b0), "r"(b1));
}
__device__ __forceinline__ void mma_fp16(float* c, const uint32_t* a,
                                         uint32_t b0, uint32_t b1) {
    asm volatile("mma.sync.aligned.m16n8k16.row.col.f32.f16.f16.f32 "
                 "{%0,%1,%2,%3}, {%4,%5,%6,%7}, {%8,%9}, {%0,%1,%2,%3};"
                 : "+f"(c[0]), "+f"(c[1]), "+f"(c[2]), "+f"(c[3])
                 : "r"(a[0]), "r"(a[1]), "r"(a[2]), "r"(a[3]), "r"(b0), "r"(b1));
}

// ---- scores kernel geometry: KC=64, 2 stages, 3 tiles (AH, AL, BH) --------
#define S_KC 64
#define S_TILE_BYTES (128 * 128)           // 128 rows x 128B (64 fp16)
#define S_STAGE_BYTES (3 * S_TILE_BYTES)   // 48 KB
#define S_NSTAGE 2
#define S_SMEM (S_NSTAGE * S_STAGE_BYTES)  // 96 KB -> 2 CTAs/SM

// ---- out kernel geometry: KC=64, 3 stages, 4 tiles (bf16 3-term path) -----
#define O_KC 64
#define O_TILE_BYTES (128 * 128)
#define O_STAGE_BYTES (4 * O_TILE_BYTES)
#define O_NSTAGE 3
#define O_SMEM (O_NSTAGE * O_STAGE_BYTES)

// ---------------------------------------------------------------------------
// Kernel 1: RoPE + hi/lo fp16 split. One thread per even/odd pair.
// Fast path: x - floorf(x) + __sincosf (phase err ~2^-21, far below split err).
// ---------------------------------------------------------------------------
__global__ __launch_bounds__(256) void rope_split_kernel(const float* __restrict__ Q) {
    size_t p = (size_t)blockIdx.x * blockDim.x + threadIdx.x;   // pair index
    int    n2  = (int)(p & (NDIM / 2 - 1));
    size_t row = p >> 12;
    int    t   = (int)(row & (TT - 1));

    const float TWO_PI_F = 6.283185307179586f;
    float freq = exp2f(-(float)n2 * (1.0f / 256.0f)) * (1.0f / TWO_PI_F);
    float x    = (float)t * freq;
    float ph   = (x - floorf(x)) * TWO_PI_F;
    float s, c;
    __sincosf(ph, &s, &c);

    float2 v = *reinterpret_cast<const float2*>(Q + row * NDIM + 2 * (size_t)n2);
    float ox = v.x * c - v.y * s;
    float oy = v.y * c + v.x * s;

    __half hx = __float2half(ox);
    __half hy = __float2half(oy);
    float lx = ox - __half2float(hx);
    float ly = oy - __half2float(hy);
    g_QH[p] = __half2(hx, hy);
    g_QL[p] = __half2(__float2half(lx), __float2half(ly));
}

// ---------------------------------------------------------------------------
// Kernel 2: trace gate factor = 0.5 + 0.5*sigmoid(mean_D(traces))
// ---------------------------------------------------------------------------
__global__ __launch_bounds__(256) void gate_kernel(const float* __restrict__ traces) {
    int row = blockIdx.x;
    float v = traces[(size_t)row * DD + threadIdx.x];
    #pragma unroll
    for (int o = 16; o; o >>= 1) v += __shfl_down_sync(0xffffffffu, v, o);
    __shared__ float ws[8];
    if ((threadIdx.x & 31) == 0) ws[threadIdx.x >> 5] = v;
    __syncthreads();
    if (threadIdx.x == 0) {
        float s = 0.f;
        #pragma unroll
        for (int i = 0; i < 8; i++) s += ws[i];
        float m = s * (1.0f / 256.0f);
        g_rowfac[row] = 0.5f + 0.5f * (1.0f / (1.0f + expf(-m)));
    }
}

// ---------------------------------------------------------------------------
// Kernel 2b: V transpose + hi/lo split:  Vt[b][d][s] = V[b][s][d]  (bf16)
// ---------------------------------------------------------------------------
__global__ __launch_bounds__(256) void vsplit_kernel(const float* __restrict__ V) {
    const int b = blockIdx.z, d0 = blockIdx.x * 32, s0 = blockIdx.y * 32;
    __shared__ float tile[32][33];
    const int tx = threadIdx.x, ty = threadIdx.y;
    #pragma unroll
    for (int i = 0; i < 4; i++) {
        int s = s0 + ty + 8 * i;
        tile[ty + 8 * i][tx] = V[((size_t)b * TT + s) * DD + d0 + tx];
    }
    __syncthreads();
    #pragma unroll
    for (int i = 0; i < 4; i++) {
        int d = d0 + ty + 8 * i;
        float v = tile[tx][ty + 8 * i];
        __nv_bfloat16 h = __float2bfloat16(v);
        size_t idx = ((size_t)b * DD + d) * TT + s0 + tx;
        g_VtH[idx] = h;
        g_VtL[idx] = __float2bfloat16(v - __bfloat162float(h));
    }
}

// ---------------------------------------------------------------------------
// Kernel 3: scores via fp16 mma.sync, 2-term split (AH*BH + AL*BH).
// CTA 128x128, 8 warps (warp tile 32x64), KC=64, 2-stage pipeline,
// ONE __syncthreads per iter. Inner kk-body de-convoyed: A frags up front,
// then B n-tiles in PAIRS (2 ldsm -> 16 MMAs) so tensor work starts early
// and ldsm is spread through the MMA stream. acc revisit distance = 8.
// ---------------------------------------------------------------------------
__global__ __launch_bounds__(256, 2) void scores_mma_kernel(const float* __restrict__ scale_p,
                                                            float* __restrict__ S) {
    const int js = blockIdx.x, jt = blockIdx.y, head = blockIdx.z;
    const int t0 = jt * 128, s0 = js * 128;
    float* Sh = S + (size_t)head * TT * TT;
    const int tid = threadIdx.x, wid = tid >> 5, lane = tid & 31;

    if (js > jt) {   // strictly above diagonal: zero fill fp32 output only
        for (int i = tid; i < 128 * 32; i += 256) {
            int r = i >> 5, c4 = (i & 31) << 2;
            *reinterpret_cast<float4*>(&Sh[(size_t)(t0 + r) * TT + s0 + c4]) =
                make_float4(0.f, 0.f, 0.f, 0.f);
        }
        return;
    }

    extern __shared__ char smem[];
    const uint32_t sbase = smem_u32(smem);

    const char* pAH = (const char*)g_QH + ((size_t)head * TT + t0) * NDIM * 2;
    const char* pAL = (const char*)g_QL + ((size_t)head * TT + t0) * NDIM * 2;
    const char* pBH = (const char*)g_QH + ((size_t)head * TT + s0) * NDIM * 2;
    const char* srcs[3] = { pAH, pAL, pBH };

    // 3 tiles * 1024 chunks / 256 threads = 12 chunks per thread
    auto load_stage = [&](int stage, int k0) {
        uint32_t sb = sbase + stage * S_STAGE_BYTES;
        size_t kb = (size_t)k0 * 2;
        #pragma unroll
        for (int rep = 0; rep < 12; rep++) {
            int idx = tid + rep * 256;
            int tile = idx >> 10, row = (idx >> 3) & 127, c = idx & 7;
            uint32_t dst = sb + tile * S_TILE_BYTES + row * 128 + ((c ^ (row & 7)) << 4);
            cp_async16(dst, srcs[tile] + (size_t)row * (NDIM * 2) + kb + c * 16);
        }
        CP_COMMIT();
    };

    load_stage(0, 0);

    const int wm = wid >> 1, wn = wid & 1;
    const int m0 = wm * 32, n0 = wn * 64;
    const int rig  = (lane & 7) + ((lane >> 3) & 1) * 8;
    const int csel = lane >> 4;
    const int xr   = lane & 7;

    // Diagonal tile: warp tile entirely above diagonal iff n0 >= m0 + 32
    const bool active = !(js == jt && n0 >= m0 + 32);

    // Hoisted ldsm row offsets and per-kk swizzle constants
    uint32_t aoff[2], boff[4];
    #pragma unroll
    for (int mt = 0; mt < 2; mt++) aoff[mt] = (uint32_t)(m0 + mt * 16 + rig) * 128;
    #pragma unroll
    for (int nt = 0; nt < 4; nt++) boff[nt] = (uint32_t)(n0 + nt * 16 + rig) * 128;
    uint32_t swzk[4];
    #pragma unroll
    for (int kk = 0; kk < 4; kk++) swzk[kk] = (uint32_t)(((2 * kk + csel) ^ xr) << 4);

    float acc[2][8][4];
    #pragma unroll
    for (int mt = 0; mt < 2; mt++)
        #pragma unroll
        for (int j = 0; j < 8; j++)
            #pragma unroll
            for (int q = 0; q < 4; q++) acc[mt][j][q] = 0.f;

    const int iters = NDIM / S_KC;  // 128
    for (int k = 0; k < iters; k++) {
        const int buf = k & 1;
        CP_WAIT(0);          // only load(k) is in flight here
        __syncthreads();     // all warps done with buf^1 from iter k-1; load(k) visible
        if (k + 1 < iters) load_stage(buf ^ 1, (k + 1) * S_KC);

        if (active) {
            const uint32_t sb = sbase + buf * S_STAGE_BYTES;
            const uint32_t aH = sb, aL = sb + S_TILE_BYTES, bH = sb + 2 * S_TILE_BYTES;

            #pragma unroll
            for (int kk = 0; kk < 4; kk++) {
                const uint32_t swz = swzk[kk];

                uint32_t ah[2][4], al[2][4];
                #pragma unroll
                for (int mt = 0; mt < 2; mt++) {
                    ldsm_x4(ah[mt], aH + aoff[mt] + swz);
                    ldsm_x4(al[mt], aL + aoff[mt] + swz);
                }
                // Process B n-tiles in pairs: 2 ldsm then 16 MMAs
                #pragma unroll
                for (int np = 0; np < 2; np++) {
                    const int n0t = 2 * np, n1t = 2 * np + 1;
                    uint32_t b0[4], b1[4];
                    ldsm_x4(b0, bH + boff[n0t] + swz);
                    ldsm_x4(b1, bH + boff[n1t] + swz);
                    // hi pass over both n-tiles (8 MMAs, distinct accs)
                    #pragma unroll
                    for (int mt = 0; mt < 2; mt++) {
                        mma_fp16(acc[mt][2 * n0t],     ah[mt], b0[0], b0[2]);
                        mma_fp16(acc[mt][2 * n0t + 1], ah[mt], b0[1], b0[3]);
                        mma_fp16(acc[mt][2 * n1t],     ah[mt], b1[0], b1[2]);
                        mma_fp16(acc[mt][2 * n1t + 1], ah[mt], b1[1], b1[3]);
                    }
                    // lo pass (revisit distance 8)
                    #pragma unroll
                    for (int mt = 0; mt < 2; mt++) {
                        mma_fp16(acc[mt][2 * n0t],     al[mt], b0[0], b0[2]);
                        mma_fp16(acc[mt][2 * n0t + 1], al[mt], b0[1], b0[3]);
                        mma_fp16(acc[mt][2 * n1t],     al[mt], b1[0], b1[2]);
                        mma_fp16(acc[mt][2 * n1t + 1], al[mt], b1[1], b1[3]);
                    }
                }
            }
        }
    }

    // Epilogue: tril(-1) * (1 + 0.01*exp(-dt/20)*scale) * rowfac
    const float sc = scale_p[0];
    const int lq = lane >> 2, lr = lane & 3;
    __nv_bfloat16* SHh = g_SH + (size_t)head * TT * TT;
    __nv_bfloat16* SLh = g_SL + (size_t)head * TT * TT;
    #pragma unroll
    for (int mt = 0; mt < 2; mt++) {
        const int tr0 = t0 + m0 + mt * 16 + lq;
        const float rf0 = g_rowfac[head * TT + tr0];
        const float rf1 = g_rowfac[head * TT + tr0 + 8];
        #pragma unroll
        for (int j = 0; j < 8; j++) {
            const int scol = s0 + n0 + j * 8 + 2 * lr;
            float2 o0, o1;
            #pragma unroll
            for (int w = 0; w < 2; w++) {
                int s = scol + w;
                float v0 = 0.f, v1 = 0.f;
                if (s < tr0) {
                    float dt = (float)(tr0 - s);
                    v0 = acc[mt][j][w] * (1.0f + 0.01f * __expf(-dt * 0.05f) * sc) * rf0;
                }
                if (s < tr0 + 8) {
                    float dt = (float)(tr0 + 8 - s);
                    v1 = acc[mt][j][2 + w] * (1.0f + 0.01f * __expf(-dt * 0.05f) * sc) * rf1;
                }
                (&o0.x)[w] = v0;
                (&o1.x)[w] = v1;
            }
            *reinterpret_cast<float2*>(&Sh[(size_t)tr0 * TT + scol]) = o0;
            *reinterpret_cast<float2*>(&Sh[(size_t)(tr0 + 8) * TT + scol]) = o1;

            __nv_bfloat16 h0x = __float2bfloat16(o0.x), h0y = __float2bfloat16(o0.y);
            __nv_bfloat16 h1x = __float2bfloat16(o1.x), h1y = __float2bfloat16(o1.y);
            *reinterpret_cast<__nv_bfloat162*>(&SHh[(size_t)tr0 * TT + scol]) =
                __nv_bfloat162(h0x, h0y);
            *reinterpret_cast<__nv_bfloat162*>(&SHh[(size_t)(tr0 + 8) * TT + scol]) =
                __nv_bfloat162(h1x, h1y);
            *reinterpret_cast<__nv_bfloat162*>(&SLh[(size_t)tr0 * TT + scol]) =
                __nv_bfloat162(__float2bfloat16(o0.x - __bfloat162float(h0x)),
                               __float2bfloat16(o0.y - __bfloat162float(h0y)));
            *reinterpret_cast<__nv_bfloat162*>(&SLh[(size_t)(tr0 + 8) * TT + scol]) =
                __nv_bfloat162(__float2bfloat16(o1.x - __bfloat162float(h1x)),
                               __float2bfloat16(o1.y - __bfloat162float(h1y)));
        }
    }
}

// ---------------------------------------------------------------------------
// Kernel 4: output = scores @ V via bf16 split MMA (unchanged 3-pass path).
// ---------------------------------------------------------------------------
__global__ __launch_bounds__(256, 1) void out_mma_kernel(float* __restrict__ O) {
    const int jd = blockIdx.x, jt = blockIdx.y, head = blockIdx.z;
    const int b  = head >> 2;
    const int t0 = jt * 128, d0 = jd * 128;
    const int tid = threadIdx.x, wid = tid >> 5, lane = tid & 31;

    extern __shared__ char smem[];
    const uint32_t sbase = smem_u32(smem);

    const char* pAH = (const char*)(g_SH  + (size_t)head * TT * TT + (size_t)t0 * TT);
    const char* pAL = (const char*)(g_SL  + (size_t)head * TT * TT + (size_t)t0 * TT);
    const char* pBH = (const char*)(g_VtH + ((size_t)b * DD + d0) * TT);
    const char* pBL = (const char*)(g_VtL + ((size_t)b * DD + d0) * TT);
    const char* srcs[4] = { pAH, pAL, pBH, pBL };

    auto load_stage = [&](int stage, int k0) {
        uint32_t sb = sbase + stage * O_STAGE_BYTES;
        size_t kb = (size_t)k0 * 2;
        #pragma unroll
        for (int rep = 0; rep < 16; rep++) {
            int idx = tid + rep * 256;
            int tile = idx >> 10, row = (idx >> 3) & 127, c = idx & 7;
            uint32_t dst = sb + tile * O_TILE_BYTES + row * 128 + ((c ^ (row & 7)) << 4);
            cp_async16(dst, srcs[tile] + (size_t)row * (TT * 2) + kb + c * 16);
        }
        CP_COMMIT();
    };

    const int iters = 2 * (jt + 1);     // (t0+128)/O_KC
    load_stage(0, 0);
    if (iters > 1) load_stage(1, O_KC);

    const int wm = wid >> 1, wn = wid & 1;
    const int m0 = wm * 32, n0 = wn * 64;
    const int rig  = (lane & 7) + ((lane >> 3) & 1) * 8;
    const int csel = lane >> 4;
    const int xr   = lane & 7;

    float acc[2][8][4];
    #pragma unroll
    for (int mt = 0; mt < 2; mt++)
        #pragma unroll
        for (int j = 0; j < 8; j++)
            #pragma unroll
            for (int q = 0; q < 4; q++) acc[mt][j][q] = 0.f;

    for (int k = 0; k < iters; k++) {
        const int buf = k % O_NSTAGE;
        if (k + 1 < iters) { CP_WAIT(1); } else { CP_WAIT(0); }
        __syncthreads();
        if (k + 2 < iters) load_stage((k + 2) % O_NSTAGE, (k + 2) * O_KC);

        const uint32_t sb = sbase + buf * O_STAGE_BYTES;
        const uint32_t aH = sb, aL = sb + O_TILE_BYTES;
        const uint32_t bH = sb + 2 * O_TILE_BYTES, bL = sb + 3 * O_TILE_BYTES;

        #pragma unroll
        for (int kk = 0; kk < 4; kk++) {
            const int c = 2 * kk + csel;
            const uint32_t swz = (uint32_t)((c ^ xr) << 4);

            uint32_t ah[2][4], al[2][4];
            #pragma unroll
            for (int mt = 0; mt < 2; mt++) {
                uint32_t roff = (uint32_t)(m0 + mt * 16 + rig) * 128 + swz;
                ldsm_x4(ah[mt], aH + roff);
                ldsm_x4(al[mt], aL + roff);
            }
            uint32_t bh[4][4], bl[4][4];
            #pragma unroll
            for (int nt = 0; nt < 4; nt++) {
                uint32_t roff = (uint32_t)(n0 + nt * 16 + rig) * 128 + swz;
                ldsm_x4(bh[nt], bH + roff);
                ldsm_x4(bl[nt], bL + roff);
            }
            #pragma unroll
            for (int mt = 0; mt < 2; mt++)
                #pragma unroll
                for (int nt = 0; nt < 4; nt++) {
                    mma_bf16(acc[mt][2 * nt],     ah[mt], bh[nt][0], bh[nt][2]);
                    mma_bf16(acc[mt][2 * nt + 1], ah[mt], bh[nt][1], bh[nt][3]);
                }
            #pragma unroll
            for (int mt = 0; mt < 2; mt++)
                #pragma unroll
                for (int nt = 0; nt < 4; nt++) {
                    mma_bf16(acc[mt][2 * nt],     ah[mt], bl[nt][0], bl[nt][2]);
                    mma_bf16(acc[mt][2 * nt + 1], ah[mt], bl[nt][1], bl[nt][3]);
                }
            #pragma unroll
            for (int mt = 0; mt < 2; mt++)
                #pragma unroll
                for (int nt = 0; nt < 4; nt++) {
                    mma_bf16(acc[mt][2 * nt],     al[mt], bh[nt][0], bh[nt][2]);
                    mma_bf16(acc[mt][2 * nt + 1], al[mt], bh[nt][1], bh[nt][3]);
                }
        }
    }

    const int lq = lane >> 2, lr = lane & 3;
    #pragma unroll
    for (int mt = 0; mt < 2; mt++) {
        const int tr0 = t0 + m0 + mt * 16 + lq;
        #pragma unroll
        for (int j = 0; j < 8; j++) {
            const int dcol = d0 + n0 + j * 8 + 2 * lr;
            float2 o0, o1;
            o0.x = acc[mt][j][0]; o0.y = acc[mt][j][1];
            o1.x = acc[mt][j][2]; o1.y = acc[mt][j][3];
            *reinterpret_cast<float2*>(&O[((size_t)head * TT + tr0) * DD + dcol]) = o0;
            *reinterpret_cast<float2*>(&O[((size_t)head * TT + tr0 + 8) * DD + dcol]) = o1;
        }
    }
}

// ---------------------------------------------------------------------------
extern "C" void kernel_launch(void* const* d_in, const int* in_sizes, int n_in,
                              void* d_out, int out_size) {
    const float* Q      = (const float*)d_in[0];
    const float* V      = (const float*)d_in[1];
    const float* traces = (const float*)d_in[2];
    const float* scale  = (const float*)d_in[3];

    float* out    = (float*)d_out;
    float* scores = out + (size_t)NHEAD * TT * DD;

    cudaFuncSetAttribute(scores_mma_kernel,
                         cudaFuncAttributeMaxDynamicSharedMemorySize, S_SMEM);
    cudaFuncSetAttribute(out_mma_kernel,
                         cudaFuncAttributeMaxDynamicSharedMemorySize, O_SMEM);

    rope_split_kernel<<<(NHEAD * TT * (NDIM / 2)) / 256, 256>>>(Q);
    gate_kernel<<<NHEAD * TT, 256>>>(traces);
    dim3 gv(DD / 32, TT / 32, 2);
    vsplit_kernel<<<gv, dim3(32, 8)>>>(V);
    dim3 gs(TT / 128, TT / 128, NHEAD);
    scores_mma_kernel<<<gs, 256, S_SMEM>>>(scale, scores);
    dim3 go(DD / 128, TT / 128, NHEAD);
    out_mma_kernel<<<go, 256, O_SMEM>>>(out);
}